// round 3
// baseline (speedup 1.0000x reference)
#include <cuda_runtime.h>
#include <math.h>

#define S_LEN  8192
#define DMODEL 2048
#define HQN    16
#define HKVN   4
#define HD     128
#define WIN    512
#define NBLK   (S_LEN / WIN)      /* 16 */
#define KVDIM  (HKVN * HD)        /* 512 */
#define QDIM   (HQN * HD)         /* 2048 */
#define W2     (2 * WIN)          /* 1024 */

typedef unsigned long long ull;

// ---------------- scratch (static device globals; no allocation) ----------------
__device__ float g_q[S_LEN * QDIM];                         // 64 MB
__device__ float g_kpad[(S_LEN + WIN) * KVDIM];             // 17 MB (rows 0..511 zero)
__device__ float g_vpad[(S_LEN + WIN) * KVDIM];             // 17 MB
__device__ float g_s[(size_t)HQN * NBLK * WIN * W2];        // 512 MB scores/probs
__device__ float g_attn[S_LEN * QDIM];                      // 64 MB

// ---------------- packed fp32x2 helpers (Blackwell FFMA2) ----------------
__device__ __forceinline__ ull ffma2(ull a, ull b, ull c) {
    ull d;
    asm("fma.rn.f32x2 %0, %1, %2, %3;" : "=l"(d) : "l"(a), "l"(b), "l"(c));
    return d;
}
__device__ __forceinline__ ull pack2(float lo, float hi) {
    ull r;
    asm("mov.b64 %0, {%1, %2};" : "=l"(r) : "f"(lo), "f"(hi));
    return r;
}
__device__ __forceinline__ void unpack2(ull v, float& lo, float& hi) {
    asm("mov.b64 {%0, %1}, %2;" : "=f"(lo), "=f"(hi) : "l"(v));
}

// ---------------- 128x128x16 fp32 GEMM tile (NN or NT) ----------------
// C[128,128] tile at (by,bx) of C = A * B  (TRANS_B=false, B is [K,N] row-major)
//                               or C = A * B^T (TRANS_B=true,  B is [N,K] row-major)
template <bool TRANS_B>
__device__ __forceinline__ void gemm_tile(
    const float* __restrict__ A, int lda,
    const float* __restrict__ B, int ldb,
    float* __restrict__ C, int ldc,
    int K, int bx, int by)
{
    __shared__ float As[16][132];
    __shared__ float Bs[16][132];

    const int tid = threadIdx.x;
    const int tr = tid >> 4;          // 0..15
    const int tc = tid & 15;          // 0..15

    const float* Abase = A + (size_t)(by * 128) * lda;
    const int ar = tid >> 2;          // 0..63
    const int ac = (tid & 3) << 2;    // 0,4,8,12

    ull acc[8][4];
#pragma unroll
    for (int i = 0; i < 8; ++i)
#pragma unroll
        for (int j = 0; j < 4; ++j) acc[i][j] = 0ull;

    for (int k0 = 0; k0 < K; k0 += 16) {
        // A tile: 128 rows x 16 k-cols, stored transposed As[k][m]
        {
            float4 v0 = *(const float4*)(Abase + (size_t)ar * lda + (k0 + ac));
            float4 v1 = *(const float4*)(Abase + (size_t)(ar + 64) * lda + (k0 + ac));
            As[ac + 0][ar] = v0.x; As[ac + 1][ar] = v0.y;
            As[ac + 2][ar] = v0.z; As[ac + 3][ar] = v0.w;
            As[ac + 0][ar + 64] = v1.x; As[ac + 1][ar + 64] = v1.y;
            As[ac + 2][ar + 64] = v1.z; As[ac + 3][ar + 64] = v1.w;
        }
        if (TRANS_B) {
            // B tile: 128 n-rows x 16 k-cols, stored transposed Bs[k][n]
            const float* Bbase = B + (size_t)(bx * 128) * ldb;
            float4 v0 = *(const float4*)(Bbase + (size_t)ar * ldb + (k0 + ac));
            float4 v1 = *(const float4*)(Bbase + (size_t)(ar + 64) * ldb + (k0 + ac));
            Bs[ac + 0][ar] = v0.x; Bs[ac + 1][ar] = v0.y;
            Bs[ac + 2][ar] = v0.z; Bs[ac + 3][ar] = v0.w;
            Bs[ac + 0][ar + 64] = v1.x; Bs[ac + 1][ar + 64] = v1.y;
            Bs[ac + 2][ar + 64] = v1.z; Bs[ac + 3][ar + 64] = v1.w;
        } else {
            // B tile: 16 k-rows x 128 n-cols, direct
            const float* Bbase = B + bx * 128;
            const int br = tid >> 5;          // 0..7
            const int bc = (tid & 31) << 2;   // 0..124
            *(float4*)&Bs[br][bc]     = *(const float4*)(Bbase + (size_t)(k0 + br) * ldb + bc);
            *(float4*)&Bs[br + 8][bc] = *(const float4*)(Bbase + (size_t)(k0 + br + 8) * ldb + bc);
        }
        __syncthreads();

#pragma unroll
        for (int kk = 0; kk < 16; ++kk) {
            float a[8], b[8];
            *(float4*)(a)     = *(const float4*)&As[kk][tr * 8];
            *(float4*)(a + 4) = *(const float4*)&As[kk][tr * 8 + 4];
            *(float4*)(b)     = *(const float4*)&Bs[kk][tc * 8];
            *(float4*)(b + 4) = *(const float4*)&Bs[kk][tc * 8 + 4];
            ull bp0 = pack2(b[0], b[1]), bp1 = pack2(b[2], b[3]);
            ull bp2 = pack2(b[4], b[5]), bp3 = pack2(b[6], b[7]);
#pragma unroll
            for (int i = 0; i < 8; ++i) {
                ull ap = pack2(a[i], a[i]);
                acc[i][0] = ffma2(ap, bp0, acc[i][0]);
                acc[i][1] = ffma2(ap, bp1, acc[i][1]);
                acc[i][2] = ffma2(ap, bp2, acc[i][2]);
                acc[i][3] = ffma2(ap, bp3, acc[i][3]);
            }
        }
        __syncthreads();
    }

    float* Cb = C + (size_t)(by * 128 + tr * 8) * ldc + bx * 128 + tc * 8;
#pragma unroll
    for (int i = 0; i < 8; ++i) {
        float o[8];
        unpack2(acc[i][0], o[0], o[1]); unpack2(acc[i][1], o[2], o[3]);
        unpack2(acc[i][2], o[4], o[5]); unpack2(acc[i][3], o[6], o[7]);
        *(float4*)(Cb + (size_t)i * ldc)     = *(const float4*)(o);
        *(float4*)(Cb + (size_t)i * ldc + 4) = *(const float4*)(o + 4);
    }
}

// ---------------- stage kernels ----------------

__global__ void zeropad_kernel() {
    int i = blockIdx.x * blockDim.x + threadIdx.x;
    if (i < WIN * KVDIM) { g_kpad[i] = 0.f; g_vpad[i] = 0.f; }
}

__global__ __launch_bounds__(256, 2)
void qproj_kernel(const float* __restrict__ hidden, const float* __restrict__ Wq) {
    gemm_tile<false>(hidden, DMODEL, Wq, QDIM, g_q, QDIM, DMODEL, blockIdx.x, blockIdx.y);
}
__global__ __launch_bounds__(256, 2)
void kproj_kernel(const float* __restrict__ hidden, const float* __restrict__ Wk) {
    gemm_tile<false>(hidden, DMODEL, Wk, KVDIM, g_kpad + (size_t)WIN * KVDIM, KVDIM,
                     DMODEL, blockIdx.x, blockIdx.y);
}
__global__ __launch_bounds__(256, 2)
void vproj_kernel(const float* __restrict__ hidden, const float* __restrict__ Wv) {
    gemm_tile<false>(hidden, DMODEL, Wv, KVDIM, g_vpad + (size_t)WIN * KVDIM, KVDIM,
                     DMODEL, blockIdx.x, blockIdx.y);
}

// scores: per (h,n)  S[512,1024] = Qb[512,128] * Kb[1024,128]^T  (raw dots, scaled in softmax)
__global__ __launch_bounds__(256, 2)
void score_kernel() {
    int z = blockIdx.z;           // h*NBLK + n
    int h = z >> 4;
    int n = z & 15;
    const float* A = g_q + (size_t)(n * WIN) * QDIM + h * HD;
    const float* B = g_kpad + (size_t)(n * WIN) * KVDIM + (h >> 2) * HD;
    float* C = g_s + (size_t)z * WIN * W2;
    gemm_tile<true>(A, QDIM, B, KVDIM, C, W2, HD, blockIdx.x, blockIdx.y);
}

// band-masked softmax over each 1024-wide score row; in-place probs (masked -> 0)
__global__ void softmax_kernel() {
    int row = blockIdx.x;                 // z*WIN + q, z = h*NBLK + n
    int q = row & (WIN - 1);
    int n = (row >> 9) & (NBLK - 1);
    float* Srow = g_s + (size_t)row * W2;
    int t = threadIdx.x;                  // 128 threads, 8 elems each

    int lo = (n == 0) ? WIN : (q + 1);    // valid ki in [lo, hi]
    int hi = q + WIN;
    const float scale = 1.0f / (float)HD; // reference's effective double-scale: /hd

    float vals[8];
    float m = -3.0e38f;
#pragma unroll
    for (int i = 0; i < 8; ++i) {
        int j = t + i * 128;
        float v = Srow[j];
        bool ok = (j >= lo) && (j <= hi);
        vals[i] = ok ? v : -3.0e38f;
        m = fmaxf(m, vals[i]);
    }
    __shared__ float redm[4], reds[4];
    for (int o = 16; o > 0; o >>= 1) m = fmaxf(m, __shfl_xor_sync(0xffffffffu, m, o));
    if ((t & 31) == 0) redm[t >> 5] = m;
    __syncthreads();
    m = fmaxf(fmaxf(redm[0], redm[1]), fmaxf(redm[2], redm[3]));

    float s = 0.f;
#pragma unroll
    for (int i = 0; i < 8; ++i) {
        float e = (vals[i] > -1.0e38f) ? __expf((vals[i] - m) * scale) : 0.f;
        vals[i] = e;
        s += e;
    }
    for (int o = 16; o > 0; o >>= 1) s += __shfl_xor_sync(0xffffffffu, s, o);
    if ((t & 31) == 0) reds[t >> 5] = s;
    __syncthreads();
    s = reds[0] + reds[1] + reds[2] + reds[3];
    float inv = 1.0f / s;
#pragma unroll
    for (int i = 0; i < 8; ++i) Srow[t + i * 128] = vals[i] * inv;
}

// PV: per (h,n)  O[512,128] = P[512,1024] * Vb[1024,128]   -> g_attn[s, h*128+d]
__global__ __launch_bounds__(256, 2)
void pv_kernel() {
    int z = blockIdx.z;
    int h = z >> 4;
    int n = z & 15;
    const float* A = g_s + (size_t)z * WIN * W2;
    const float* B = g_vpad + (size_t)(n * WIN) * KVDIM + (h >> 2) * HD;
    float* C = g_attn + (size_t)(n * WIN) * QDIM + h * HD;
    gemm_tile<false>(A, W2, B, KVDIM, C, QDIM, W2, blockIdx.x /*0*/, blockIdx.y);
}

__global__ __launch_bounds__(256, 2)
void oproj_kernel(const float* __restrict__ Wo, float* __restrict__ out) {
    gemm_tile<false>(g_attn, QDIM, Wo, DMODEL, out, DMODEL, DMODEL, blockIdx.x, blockIdx.y);
}

// ---------------- launcher (graph-capturable: kernels only) ----------------
extern "C" void kernel_launch(void* const* d_in, const int* in_sizes, int n_in,
                              void* d_out, int out_size) {
    const float* hidden = (const float*)d_in[0];
    const float* Wq = (const float*)d_in[1];
    const float* Wk = (const float*)d_in[2];
    const float* Wv = (const float*)d_in[3];
    const float* Wo = (const float*)d_in[4];
    float* out = (float*)d_out;

    dim3 blk(256);
    zeropad_kernel<<<(WIN * KVDIM + 255) / 256, 256>>>();
    qproj_kernel<<<dim3(QDIM / 128, S_LEN / 128), blk>>>(hidden, Wq);     // (16,64)
    kproj_kernel<<<dim3(KVDIM / 128, S_LEN / 128), blk>>>(hidden, Wk);    // (4,64)
    vproj_kernel<<<dim3(KVDIM / 128, S_LEN / 128), blk>>>(hidden, Wv);    // (4,64)
    score_kernel<<<dim3(W2 / 128, WIN / 128, HQN * NBLK), blk>>>();       // (8,4,256)
    softmax_kernel<<<HQN * NBLK * WIN, 128>>>();                          // 131072 rows
    pv_kernel<<<dim3(1, WIN / 128, HQN * NBLK), blk>>>();                 // (1,4,256)
    oproj_kernel<<<dim3(DMODEL / 128, S_LEN / 128), blk>>>(Wo, out);      // (16,64)
}

// round 5
// speedup vs baseline: 2.4056x; 2.4056x over previous
#include <cuda_runtime.h>
#include <cstdint>
#include <math.h>

#define S_LEN  8192
#define DMODEL 2048
#define HQN    16
#define HKVN   4
#define HD     128
#define WIN    512
#define NBLK   (S_LEN / WIN)      /* 16 */
#define KVDIM  (HKVN * HD)        /* 512 */
#define QDIM   (HQN * HD)         /* 2048 */
#define W2     (2 * WIN)          /* 1024 */

#define ASTR    20                /* A / BT-B smem row stride (floats) */
#define BSTR_NN 136               /* NN-B smem row stride (floats)     */
#define BSMAX   2560              /* max B buffer floats: 128*20       */

// ---------------- scratch (static device globals; no allocation) ----------------
__device__ float g_q[S_LEN * QDIM];                         // 64 MB
__device__ float g_kpad[(S_LEN + WIN) * KVDIM];             // 17 MB (rows 0..511 zero)
__device__ float g_vpad[(S_LEN + WIN) * KVDIM];             // 17 MB
__device__ float g_s[(size_t)HQN * NBLK * WIN * W2];        // 512 MB scores/probs
__device__ float g_attn[S_LEN * QDIM];                      // 64 MB
// tf32-rounded copies of inputs
__device__ float g_h[S_LEN * DMODEL];                       // 64 MB
__device__ float g_wq[DMODEL * QDIM];                       // 16 MB
__device__ float g_wk[DMODEL * KVDIM];                      //  4 MB
__device__ float g_wv[DMODEL * KVDIM];                      //  4 MB
__device__ float g_wo[QDIM * DMODEL];                       // 16 MB

// ---------------- helpers ----------------
__device__ __forceinline__ float to_tf32(float x) {
    uint32_t u;
    asm("cvt.rna.tf32.f32 %0, %1;" : "=r"(u) : "f"(x));
    return __uint_as_float(u);
}
__device__ __forceinline__ uint32_t smem_u32(const void* p) {
    uint32_t a;
    asm("{ .reg .u64 t; cvta.to.shared.u64 t, %1; cvt.u32.u64 %0, t; }" : "=r"(a) : "l"(p));
    return a;
}
__device__ __forceinline__ void cp16(uint32_t dst, const void* src) {
    asm volatile("cp.async.cg.shared.global [%0], [%1], 16;" :: "r"(dst), "l"(src) : "memory");
}
__device__ __forceinline__ void mma_tf32(float* c, const uint32_t* a, const uint32_t* b) {
    asm volatile(
        "mma.sync.aligned.m16n8k8.row.col.f32.tf32.tf32.f32 "
        "{%0,%1,%2,%3}, {%4,%5,%6,%7}, {%8,%9}, {%0,%1,%2,%3};"
        : "+f"(c[0]), "+f"(c[1]), "+f"(c[2]), "+f"(c[3])
        : "r"(a[0]), "r"(a[1]), "r"(a[2]), "r"(a[3]), "r"(b[0]), "r"(b[1]));
}

// ---------------- mma.sync tf32 128x128 GEMM tile ----------------
// C tile (by,bx) of: C = A * B   (BT=false: B is [K,N] row-major)
//                    C = A * B^T (BT=true:  B is [N,K] row-major)
// ROUND: round outputs to tf32 (when C feeds a later MMA as operand)
template <bool BT, bool ROUND>
__device__ __forceinline__ void gemm_mma(
    const float* __restrict__ A, int lda,
    const float* __restrict__ B, int ldb,
    float* __restrict__ C, int ldc,
    int K, int bx, int by)
{
    __shared__ float As[2][128 * ASTR];
    __shared__ float Bs[2][BSMAX];

    const int tid = threadIdx.x;
    const int lane = tid & 31;
    const int w = tid >> 5;
    const int wm = (w & 3) * 32;      // warp m offset (warp tile 32x64)
    const int wn = (w >> 2) * 64;     // warp n offset

    const float* Ag = A + (size_t)(by * 128) * lda;
    const float* BgT = B + (size_t)(bx * 128) * ldb;     // BT path base
    const float* BgN = B + bx * 128;                     // NN path base

    const uint32_t as_base = smem_u32(As);
    const uint32_t bs_base = smem_u32(Bs);

    // loader indices: A (and BT-B): 128 rows x 16 cols, 2x 16B per thread
    const int arow = tid >> 1;
    const int acol = (tid & 1) * 8;
    // NN-B: 16 rows x 128 cols, 2x consecutive 16B per thread
    const int bid = tid * 2;
    const int brow = bid >> 5;
    const int bcol = (bid & 31) * 4;

    float acc[2][8][4];
#pragma unroll
    for (int mt = 0; mt < 2; ++mt)
#pragma unroll
        for (int nt = 0; nt < 8; ++nt)
#pragma unroll
            for (int i = 0; i < 4; ++i) acc[mt][nt][i] = 0.f;

    const int nch = K >> 4;

    auto issue = [&](int c, int s) {
        const int k0 = c << 4;
        {
            const float* src = Ag + (size_t)arow * lda + k0 + acol;
            uint32_t d = as_base + (uint32_t)(s * 128 * ASTR + arow * ASTR + acol) * 4u;
            cp16(d, src);
            cp16(d + 16, src + 4);
        }
        if (BT) {
            const float* src = BgT + (size_t)arow * ldb + k0 + acol;
            uint32_t d = bs_base + (uint32_t)(s * BSMAX + arow * ASTR + acol) * 4u;
            cp16(d, src);
            cp16(d + 16, src + 4);
        } else {
            const float* src = BgN + (size_t)(k0 + brow) * ldb + bcol;
            uint32_t d = bs_base + (uint32_t)(s * BSMAX + brow * BSTR_NN + bcol) * 4u;
            cp16(d, src);
            cp16(d + 16, src + 4);
        }
        asm volatile("cp.async.commit_group;" ::: "memory");
    };

    issue(0, 0);
    for (int c = 0; c < nch; ++c) {
        const int s = c & 1;
        if (c + 1 < nch) {
            issue(c + 1, s ^ 1);
            asm volatile("cp.async.wait_group 1;" ::: "memory");
        } else {
            asm volatile("cp.async.wait_group 0;" ::: "memory");
        }
        __syncthreads();

        const int r = lane >> 2, cc = lane & 3;
#pragma unroll
        for (int ks = 0; ks < 2; ++ks) {
            uint32_t a[2][4], b[8][2];
#pragma unroll
            for (int mt = 0; mt < 2; ++mt) {
                const float* ab = &As[s][(wm + mt * 16 + r) * ASTR + ks * 8 + cc];
                a[mt][0] = __float_as_uint(ab[0]);
                a[mt][1] = __float_as_uint(ab[8 * ASTR]);
                a[mt][2] = __float_as_uint(ab[4]);
                a[mt][3] = __float_as_uint(ab[8 * ASTR + 4]);
            }
#pragma unroll
            for (int nt = 0; nt < 8; ++nt) {
                if (BT) {
                    const float* bb = &Bs[s][(wn + nt * 8 + r) * ASTR + ks * 8 + cc];
                    b[nt][0] = __float_as_uint(bb[0]);
                    b[nt][1] = __float_as_uint(bb[4]);
                } else {
                    const float* bb = &Bs[s][(ks * 8 + cc) * BSTR_NN + wn + nt * 8 + r];
                    b[nt][0] = __float_as_uint(bb[0]);
                    b[nt][1] = __float_as_uint(bb[4 * BSTR_NN]);
                }
            }
#pragma unroll
            for (int mt = 0; mt < 2; ++mt)
#pragma unroll
                for (int nt = 0; nt < 8; ++nt)
                    mma_tf32(acc[mt][nt], a[mt], b[nt]);
        }
        __syncthreads();
    }

    // ---- epilogue ----
    float* Cb = C + (size_t)(by * 128) * ldc + bx * 128;
    const int r = lane >> 2, c2 = (lane & 3) * 2;
#pragma unroll
    for (int mt = 0; mt < 2; ++mt) {
        const int row = wm + mt * 16 + r;
#pragma unroll
        for (int nt = 0; nt < 8; ++nt) {
            const int col = wn + nt * 8 + c2;
            float v0 = acc[mt][nt][0], v1 = acc[mt][nt][1];
            float v2 = acc[mt][nt][2], v3 = acc[mt][nt][3];
            if (ROUND) { v0 = to_tf32(v0); v1 = to_tf32(v1); v2 = to_tf32(v2); v3 = to_tf32(v3); }
            *(float2*)(Cb + (size_t)row * ldc + col) = make_float2(v0, v1);
            *(float2*)(Cb + (size_t)(row + 8) * ldc + col) = make_float2(v2, v3);
        }
    }
}

// ---------------- stage kernels ----------------
__global__ void zeropad_kernel() {
    int i = blockIdx.x * blockDim.x + threadIdx.x;
    if (i < WIN * KVDIM) { g_kpad[i] = 0.f; g_vpad[i] = 0.f; }
}

__global__ void round_tf32_kernel(const float* __restrict__ in, float* __restrict__ out, int n) {
    int i = (blockIdx.x * blockDim.x + threadIdx.x) * 4;
    if (i < n) {
        float4 v = *(const float4*)(in + i);
        v.x = to_tf32(v.x); v.y = to_tf32(v.y);
        v.z = to_tf32(v.z); v.w = to_tf32(v.w);
        *(float4*)(out + i) = v;
    }
}

__global__ __launch_bounds__(256)
void qproj_mma(void) {
    gemm_mma<false, true>(g_h, DMODEL, g_wq, QDIM, g_q, QDIM, DMODEL, blockIdx.x, blockIdx.y);
}
__global__ __launch_bounds__(256)
void kproj_mma(void) {
    gemm_mma<false, true>(g_h, DMODEL, g_wk, KVDIM, g_kpad + (size_t)WIN * KVDIM, KVDIM,
                          DMODEL, blockIdx.x, blockIdx.y);
}
__global__ __launch_bounds__(256)
void vproj_mma(void) {
    gemm_mma<false, true>(g_h, DMODEL, g_wv, KVDIM, g_vpad + (size_t)WIN * KVDIM, KVDIM,
                          DMODEL, blockIdx.x, blockIdx.y);
}
// scores: per (h,n)  S[512,1024] = Qb[512,128] * Kb[1024,128]^T
__global__ __launch_bounds__(256)
void score_mma(void) {
    int z = blockIdx.z, h = z >> 4, n = z & 15;
    const float* A = g_q + (size_t)(n * WIN) * QDIM + h * HD;
    const float* B = g_kpad + (size_t)(n * WIN) * KVDIM + (h >> 2) * HD;
    float* C = g_s + (size_t)z * WIN * W2;
    gemm_mma<true, false>(A, QDIM, B, KVDIM, C, W2, HD, blockIdx.x, blockIdx.y);
}
// PV: per (h,n)  O[512,128] = P[512,1024] * Vb[1024,128]
__global__ __launch_bounds__(256)
void pv_mma(void) {
    int z = blockIdx.z, h = z >> 4, n = z & 15;
    const float* A = g_s + (size_t)z * WIN * W2;
    const float* B = g_vpad + (size_t)(n * WIN) * KVDIM + (h >> 2) * HD;
    float* C = g_attn + (size_t)(n * WIN) * QDIM + h * HD;
    gemm_mma<false, true>(A, W2, B, KVDIM, C, QDIM, W2, 0, blockIdx.y);
}
__global__ __launch_bounds__(256)
void oproj_mma(float* __restrict__ out) {
    gemm_mma<false, false>(g_attn, QDIM, g_wo, DMODEL, out, DMODEL, DMODEL,
                           blockIdx.x, blockIdx.y);
}

// band-masked softmax over each 1024-wide score row; probs rounded to tf32
__global__ void softmax_kernel() {
    int row = blockIdx.x;                 // z*WIN + q, z = h*NBLK + n
    int q = row & (WIN - 1);
    int n = (row >> 9) & (NBLK - 1);
    float* Srow = g_s + (size_t)row * W2;
    int t = threadIdx.x;                  // 128 threads, 8 elems each

    int lo = (n == 0) ? WIN : (q + 1);    // valid ki in [lo, hi]
    int hi = q + WIN;
    const float scale = 1.0f / (float)HD; // reference's effective double-scale: /hd

    float vals[8];
    float m = -3.0e38f;
#pragma unroll
    for (int i = 0; i < 8; ++i) {
        int j = t + i * 128;
        float v = Srow[j];
        bool ok = (j >= lo) && (j <= hi);
        vals[i] = ok ? v : -3.0e38f;
        m = fmaxf(m, vals[i]);
    }
    __shared__ float redm[4], reds[4];
    for (int o = 16; o > 0; o >>= 1) m = fmaxf(m, __shfl_xor_sync(0xffffffffu, m, o));
    if ((t & 31) == 0) redm[t >> 5] = m;
    __syncthreads();
    m = fmaxf(fmaxf(redm[0], redm[1]), fmaxf(redm[2], redm[3]));

    float s = 0.f;
#pragma unroll
    for (int i = 0; i < 8; ++i) {
        float e = (vals[i] > -1.0e38f) ? __expf((vals[i] - m) * scale) : 0.f;
        vals[i] = e;
        s += e;
    }
    for (int o = 16; o > 0; o >>= 1) s += __shfl_xor_sync(0xffffffffu, s, o);
    if ((t & 31) == 0) reds[t >> 5] = s;
    __syncthreads();
    s = reds[0] + reds[1] + reds[2] + reds[3];
    float inv = 1.0f / s;
#pragma unroll
    for (int i = 0; i < 8; ++i) Srow[t + i * 128] = to_tf32(vals[i] * inv);
}

// ---------------- launcher (graph-capturable: kernels only) ----------------
extern "C" void kernel_launch(void* const* d_in, const int* in_sizes, int n_in,
                              void* d_out, int out_size) {
    const float* hidden = (const float*)d_in[0];
    const float* Wq = (const float*)d_in[1];
    const float* Wk = (const float*)d_in[2];
    const float* Wv = (const float*)d_in[3];
    const float* Wo = (const float*)d_in[4];
    float* out = (float*)d_out;

    float* gh; float* gwq; float* gwk; float* gwv; float* gwo;
    cudaGetSymbolAddress((void**)&gh,  g_h);
    cudaGetSymbolAddress((void**)&gwq, g_wq);
    cudaGetSymbolAddress((void**)&gwk, g_wk);
    cudaGetSymbolAddress((void**)&gwv, g_wv);
    cudaGetSymbolAddress((void**)&gwo, g_wo);

    dim3 blk(256);
    // tf32-round all MMA inputs (zero-mean rounding; removes truncation bias)
    round_tf32_kernel<<<(S_LEN * DMODEL / 4 + 255) / 256, 256>>>(hidden, gh, S_LEN * DMODEL);
    round_tf32_kernel<<<(DMODEL * QDIM  / 4 + 255) / 256, 256>>>(Wq, gwq, DMODEL * QDIM);
    round_tf32_kernel<<<(DMODEL * KVDIM / 4 + 255) / 256, 256>>>(Wk, gwk, DMODEL * KVDIM);
    round_tf32_kernel<<<(DMODEL * KVDIM / 4 + 255) / 256, 256>>>(Wv, gwv, DMODEL * KVDIM);
    round_tf32_kernel<<<(QDIM * DMODEL  / 4 + 255) / 256, 256>>>(Wo, gwo, QDIM * DMODEL);
    zeropad_kernel<<<(WIN * KVDIM + 255) / 256, 256>>>();

    qproj_mma<<<dim3(QDIM / 128, S_LEN / 128), blk>>>();                 // (16,64)
    kproj_mma<<<dim3(KVDIM / 128, S_LEN / 128), blk>>>();                // (4,64)
    vproj_mma<<<dim3(KVDIM / 128, S_LEN / 128), blk>>>();                // (4,64)
    score_mma<<<dim3(W2 / 128, WIN / 128, HQN * NBLK), blk>>>();         // (8,4,256)
    softmax_kernel<<<HQN * NBLK * WIN, 128>>>();                         // 131072 rows
    pv_mma<<<dim3(1, WIN / 128, HQN * NBLK), blk>>>();                   // (1,4,256)
    oproj_mma<<<dim3(DMODEL / 128, S_LEN / 128), blk>>>(out);            // (16,64)
}

// round 6
// speedup vs baseline: 2.8104x; 1.1683x over previous
#include <cuda_runtime.h>
#include <cstdint>
#include <math.h>

#define S_LEN  8192
#define DMODEL 2048
#define HQN    16
#define HKVN   4
#define HD     128
#define WIN    512
#define NBLK   (S_LEN / WIN)      /* 16 */
#define KVDIM  (HKVN * HD)        /* 512 */
#define QDIM   (HQN * HD)         /* 2048 */

#define ASTR    20                /* A / BT-B smem row stride (floats) */
#define BSTR_NN 136               /* NN-B smem row stride (floats)     */
#define BSMAX   2560              /* max B buffer floats: 128*20       */

// ---------------- scratch (static device globals; no allocation) ----------------
__device__ float g_q[S_LEN * QDIM];                         // 64 MB (tf32, per-head cols)
__device__ float g_kpad[(S_LEN + WIN) * KVDIM];             // 17 MB (rows 0..511 zero)
__device__ float g_vpad[(S_LEN + WIN) * KVDIM];             // 17 MB
__device__ float g_attn[S_LEN * QDIM];                      // 64 MB
// tf32-rounded copies of inputs
__device__ float g_h[S_LEN * DMODEL];                       // 64 MB
__device__ float g_wq[DMODEL * QDIM];                       // 16 MB
__device__ float g_wk[DMODEL * KVDIM];                      //  4 MB
__device__ float g_wv[DMODEL * KVDIM];                      //  4 MB
__device__ float g_wo[QDIM * DMODEL];                       // 16 MB

// ---------------- helpers ----------------
__device__ __forceinline__ float to_tf32(float x) {
    uint32_t u;
    asm("cvt.rna.tf32.f32 %0, %1;" : "=r"(u) : "f"(x));
    return __uint_as_float(u);
}
__device__ __forceinline__ uint32_t smem_u32(const void* p) {
    uint32_t a;
    asm("{ .reg .u64 t; cvta.to.shared.u64 t, %1; cvt.u32.u64 %0, t; }" : "=r"(a) : "l"(p));
    return a;
}
__device__ __forceinline__ void cp16(uint32_t dst, const void* src) {
    asm volatile("cp.async.cg.shared.global [%0], [%1], 16;" :: "r"(dst), "l"(src) : "memory");
}
#define CP_COMMIT() asm volatile("cp.async.commit_group;" ::: "memory")
__device__ __forceinline__ void mma_tf32(float* c, const uint32_t* a, const uint32_t* b) {
    asm volatile(
        "mma.sync.aligned.m16n8k8.row.col.f32.tf32.tf32.f32 "
        "{%0,%1,%2,%3}, {%4,%5,%6,%7}, {%8,%9}, {%0,%1,%2,%3};"
        : "+f"(c[0]), "+f"(c[1]), "+f"(c[2]), "+f"(c[3])
        : "r"(a[0]), "r"(a[1]), "r"(a[2]), "r"(a[3]), "r"(b[0]), "r"(b[1]));
}

// ---------------- mma.sync tf32 128x128 GEMM tile (round-5, proven) ----------------
template <bool BT, bool ROUND>
__device__ __forceinline__ void gemm_mma(
    const float* __restrict__ A, int lda,
    const float* __restrict__ B, int ldb,
    float* __restrict__ C, int ldc,
    int K, int bx, int by)
{
    __shared__ float As[2][128 * ASTR];
    __shared__ float Bs[2][BSMAX];

    const int tid = threadIdx.x;
    const int lane = tid & 31;
    const int w = tid >> 5;
    const int wm = (w & 3) * 32;
    const int wn = (w >> 2) * 64;

    const float* Ag = A + (size_t)(by * 128) * lda;
    const float* BgT = B + (size_t)(bx * 128) * ldb;
    const float* BgN = B + bx * 128;

    const uint32_t as_base = smem_u32(As);
    const uint32_t bs_base = smem_u32(Bs);

    const int arow = tid >> 1;
    const int acol = (tid & 1) * 8;
    const int bid = tid * 2;
    const int brow = bid >> 5;
    const int bcol = (bid & 31) * 4;

    float acc[2][8][4];
#pragma unroll
    for (int mt = 0; mt < 2; ++mt)
#pragma unroll
        for (int nt = 0; nt < 8; ++nt)
#pragma unroll
            for (int i = 0; i < 4; ++i) acc[mt][nt][i] = 0.f;

    const int nch = K >> 4;

    auto issue = [&](int c, int s) {
        const int k0 = c << 4;
        {
            const float* src = Ag + (size_t)arow * lda + k0 + acol;
            uint32_t d = as_base + (uint32_t)(s * 128 * ASTR + arow * ASTR + acol) * 4u;
            cp16(d, src);
            cp16(d + 16, src + 4);
        }
        if (BT) {
            const float* src = BgT + (size_t)arow * ldb + k0 + acol;
            uint32_t d = bs_base + (uint32_t)(s * BSMAX + arow * ASTR + acol) * 4u;
            cp16(d, src);
            cp16(d + 16, src + 4);
        } else {
            const float* src = BgN + (size_t)(k0 + brow) * ldb + bcol;
            uint32_t d = bs_base + (uint32_t)(s * BSMAX + brow * BSTR_NN + bcol) * 4u;
            cp16(d, src);
            cp16(d + 16, src + 4);
        }
        CP_COMMIT();
    };

    issue(0, 0);
    for (int c = 0; c < nch; ++c) {
        const int s = c & 1;
        if (c + 1 < nch) {
            issue(c + 1, s ^ 1);
            asm volatile("cp.async.wait_group 1;" ::: "memory");
        } else {
            asm volatile("cp.async.wait_group 0;" ::: "memory");
        }
        __syncthreads();

        const int r = lane >> 2, cc = lane & 3;
#pragma unroll
        for (int ks = 0; ks < 2; ++ks) {
            uint32_t a[2][4], b[8][2];
#pragma unroll
            for (int mt = 0; mt < 2; ++mt) {
                const float* ab = &As[s][(wm + mt * 16 + r) * ASTR + ks * 8 + cc];
                a[mt][0] = __float_as_uint(ab[0]);
                a[mt][1] = __float_as_uint(ab[8 * ASTR]);
                a[mt][2] = __float_as_uint(ab[4]);
                a[mt][3] = __float_as_uint(ab[8 * ASTR + 4]);
            }
#pragma unroll
            for (int nt = 0; nt < 8; ++nt) {
                if (BT) {
                    const float* bb = &Bs[s][(wn + nt * 8 + r) * ASTR + ks * 8 + cc];
                    b[nt][0] = __float_as_uint(bb[0]);
                    b[nt][1] = __float_as_uint(bb[4]);
                } else {
                    const float* bb = &Bs[s][(ks * 8 + cc) * BSTR_NN + wn + nt * 8 + r];
                    b[nt][0] = __float_as_uint(bb[0]);
                    b[nt][1] = __float_as_uint(bb[4 * BSTR_NN]);
                }
            }
#pragma unroll
            for (int mt = 0; mt < 2; ++mt)
#pragma unroll
                for (int nt = 0; nt < 8; ++nt)
                    mma_tf32(acc[mt][nt], a[mt], b[nt]);
        }
        __syncthreads();
    }

    float* Cb = C + (size_t)(by * 128) * ldc + bx * 128;
    const int r = lane >> 2, c2 = (lane & 3) * 2;
#pragma unroll
    for (int mt = 0; mt < 2; ++mt) {
        const int row = wm + mt * 16 + r;
#pragma unroll
        for (int nt = 0; nt < 8; ++nt) {
            const int col = wn + nt * 8 + c2;
            float v0 = acc[mt][nt][0], v1 = acc[mt][nt][1];
            float v2 = acc[mt][nt][2], v3 = acc[mt][nt][3];
            if (ROUND) { v0 = to_tf32(v0); v1 = to_tf32(v1); v2 = to_tf32(v2); v3 = to_tf32(v3); }
            *(float2*)(Cb + (size_t)row * ldc + col) = make_float2(v0, v1);
            *(float2*)(Cb + (size_t)(row + 8) * ldc + col) = make_float2(v2, v3);
        }
    }
}

// ---------------- fused flash attention (band window, online softmax) ----------------
// grid (64 qblocks, 16 heads), 256 threads (8 warps x 16 query rows)
#define QSTR 132
#define KSTR 132
#define VSTR 136
#define SM_Q 0
#define SM_K (128 * QSTR)                       /* 16896 */
#define SM_V (SM_K + 2 * 64 * KSTR)             /* 33792 floats after SM_K */
#define FA_SMEM_FLOATS (SM_V + 2 * 64 * VSTR)   /* 51200 floats */
#define FA_SMEM_BYTES  (FA_SMEM_FLOATS * 4)     /* 204800 B */
#define NCH 10

__global__ __launch_bounds__(256, 1)
void fattn_kernel() {
    extern __shared__ float sm[];
    const int qb = blockIdx.x, h = blockIdx.y;
    const int tid = threadIdx.x, lane = tid & 31, w = tid >> 5;
    const uint32_t sbase = smem_u32(sm);

    const float* Qg = g_q + (size_t)(qb * 128) * QDIM + h * HD;
    const float* Kg = g_kpad + (size_t)(qb * 128) * KVDIM + (h >> 2) * HD;
    const float* Vg = g_vpad + (size_t)(qb * 128) * KVDIM + (h >> 2) * HD;

    const int qr = tid >> 1, qh = tid & 1;   // Q loader: row, half
    const int kr = tid >> 2, kq = tid & 3;   // K/V loader: row, quarter

    auto issueQ = [&]() {
        const float* src = Qg + (size_t)qr * QDIM + qh * 64;
        uint32_t d = sbase + (uint32_t)(qr * QSTR + qh * 64) * 4u;
#pragma unroll
        for (int j = 0; j < 8; ++j) {
            cp16(d + j * 32, src + j * 8);
            cp16(d + j * 32 + 16, src + j * 8 + 4);
        }
    };
    auto issueKV = [&](int c) {
        const int s = c & 1;
        const float* ks = Kg + (size_t)(c * 64 + kr) * KVDIM + kq * 32;
        uint32_t kd = sbase + (uint32_t)(SM_K + s * 64 * KSTR + kr * KSTR + kq * 32) * 4u;
#pragma unroll
        for (int j = 0; j < 8; ++j) cp16(kd + j * 16, ks + j * 4);
        const float* vs = Vg + (size_t)(c * 64 + kr) * KVDIM + kq * 32;
        uint32_t vd = sbase + (uint32_t)(SM_V + s * 64 * VSTR + kr * VSTR + kq * 32) * 4u;
#pragma unroll
        for (int j = 0; j < 8; ++j) cp16(vd + j * 16, vs + j * 4);
    };

    const int r = lane >> 2, cl = lane & 3;
    const int ql0 = w * 16 + r, ql1 = ql0 + 8;    // local query rows
    const int jmin = 512 - qb * 128;              // off >= jmin (key exists)
    const float scale = 1.0f / (float)HD;

    float accO[16][4];
#pragma unroll
    for (int nt = 0; nt < 16; ++nt)
#pragma unroll
        for (int i = 0; i < 4; ++i) accO[nt][i] = 0.f;
    float m0 = -3.0e38f, m1 = -3.0e38f, l0 = 0.f, l1 = 0.f;

    const int cstart = (qb < 4) ? (8 - 2 * qb) : 0;

    issueQ(); issueKV(cstart); CP_COMMIT();
    if (cstart + 1 < NCH) { issueKV(cstart + 1); CP_COMMIT(); }

#pragma unroll 1
    for (int c = cstart; c < NCH; ++c) {
        if (c + 1 < NCH) asm volatile("cp.async.wait_group 1;" ::: "memory");
        else             asm volatile("cp.async.wait_group 0;" ::: "memory");
        __syncthreads();
        const int s = c & 1;
        const float* Ksb = sm + SM_K + s * 64 * KSTR;
        const float* Vsb = sm + SM_V + s * 64 * VSTR;

        // ---- S = Q (128xHD) * Kchunk(64xHD)^T ----
        float accS[8][4];
#pragma unroll
        for (int nt = 0; nt < 8; ++nt)
#pragma unroll
            for (int i = 0; i < 4; ++i) accS[nt][i] = 0.f;
#pragma unroll
        for (int ks = 0; ks < 16; ++ks) {
            uint32_t a[4];
            const float* ab = sm + (w * 16 + r) * QSTR + ks * 8 + cl;
            a[0] = __float_as_uint(ab[0]);
            a[1] = __float_as_uint(ab[8 * QSTR]);
            a[2] = __float_as_uint(ab[4]);
            a[3] = __float_as_uint(ab[8 * QSTR + 4]);
#pragma unroll
            for (int nt = 0; nt < 8; ++nt) {
                const float* bb = Ksb + (nt * 8 + r) * KSTR + ks * 8 + cl;
                uint32_t b[2] = { __float_as_uint(bb[0]), __float_as_uint(bb[4]) };
                mma_tf32(accS[nt], a, b);
            }
        }

        // ---- band mask + chunk row max ----
        float mc0 = -3.0e38f, mc1 = -3.0e38f;
#pragma unroll
        for (int nt = 0; nt < 8; ++nt) {
            const int off0 = c * 64 + nt * 8 + 2 * cl;
            const int off1 = off0 + 1;
            bool v00 = (off0 > ql0) && (off0 <= ql0 + 512) && (off0 >= jmin);
            bool v01 = (off1 > ql0) && (off1 <= ql0 + 512) && (off1 >= jmin);
            bool v10 = (off0 > ql1) && (off0 <= ql1 + 512) && (off0 >= jmin);
            bool v11 = (off1 > ql1) && (off1 <= ql1 + 512) && (off1 >= jmin);
            accS[nt][0] = v00 ? accS[nt][0] : -3.0e38f;
            accS[nt][1] = v01 ? accS[nt][1] : -3.0e38f;
            accS[nt][2] = v10 ? accS[nt][2] : -3.0e38f;
            accS[nt][3] = v11 ? accS[nt][3] : -3.0e38f;
            mc0 = fmaxf(mc0, fmaxf(accS[nt][0], accS[nt][1]));
            mc1 = fmaxf(mc1, fmaxf(accS[nt][2], accS[nt][3]));
        }
        mc0 = fmaxf(mc0, __shfl_xor_sync(0xffffffffu, mc0, 1));
        mc0 = fmaxf(mc0, __shfl_xor_sync(0xffffffffu, mc0, 2));
        mc1 = fmaxf(mc1, __shfl_xor_sync(0xffffffffu, mc1, 1));
        mc1 = fmaxf(mc1, __shfl_xor_sync(0xffffffffu, mc1, 2));

        // ---- online softmax update ----
        const float mn0 = fmaxf(m0, mc0), mn1 = fmaxf(m1, mc1);
        const float f0 = __expf((m0 - mn0) * scale);
        const float f1 = __expf((m1 - mn1) * scale);
        float s0 = 0.f, s1 = 0.f;
#pragma unroll
        for (int nt = 0; nt < 8; ++nt) {
            float e0 = (accS[nt][0] > -1.0e38f) ? __expf((accS[nt][0] - mn0) * scale) : 0.f;
            float e1 = (accS[nt][1] > -1.0e38f) ? __expf((accS[nt][1] - mn0) * scale) : 0.f;
            float e2 = (accS[nt][2] > -1.0e38f) ? __expf((accS[nt][2] - mn1) * scale) : 0.f;
            float e3 = (accS[nt][3] > -1.0e38f) ? __expf((accS[nt][3] - mn1) * scale) : 0.f;
            s0 += e0 + e1; s1 += e2 + e3;
            accS[nt][0] = to_tf32(e0); accS[nt][1] = to_tf32(e1);
            accS[nt][2] = to_tf32(e2); accS[nt][3] = to_tf32(e3);
        }
        s0 += __shfl_xor_sync(0xffffffffu, s0, 1);
        s0 += __shfl_xor_sync(0xffffffffu, s0, 2);
        s1 += __shfl_xor_sync(0xffffffffu, s1, 1);
        s1 += __shfl_xor_sync(0xffffffffu, s1, 2);
        l0 = l0 * f0 + s0; l1 = l1 * f1 + s1;
        m0 = mn0; m1 = mn1;
#pragma unroll
        for (int nt = 0; nt < 16; ++nt) {
            accO[nt][0] *= f0; accO[nt][1] *= f0;
            accO[nt][2] *= f1; accO[nt][3] *= f1;
        }

        // ---- O += P (128x64) * Vchunk (64xHD) ----
        const uint32_t srcl0 = (lane & ~3u) | ((uint32_t)(lane & 3) >> 1);
        const uint32_t srcl1 = srcl0 + 2;
        const bool odd = lane & 1;
#pragma unroll
        for (int ks = 0; ks < 8; ++ks) {
            // convert C-frag cols {2c,2c+1} -> A-frag cols {c, c+4} via shuffles
            float p0 = accS[ks][0], p1 = accS[ks][1];
            float p2 = accS[ks][2], p3 = accS[ks][3];
            float t00 = __shfl_sync(0xffffffffu, p0, srcl0);
            float t01 = __shfl_sync(0xffffffffu, p1, srcl0);
            float t10 = __shfl_sync(0xffffffffu, p2, srcl0);
            float t11 = __shfl_sync(0xffffffffu, p3, srcl0);
            float t20 = __shfl_sync(0xffffffffu, p0, srcl1);
            float t21 = __shfl_sync(0xffffffffu, p1, srcl1);
            float t30 = __shfl_sync(0xffffffffu, p2, srcl1);
            float t31 = __shfl_sync(0xffffffffu, p3, srcl1);
            uint32_t a[4];
            a[0] = __float_as_uint(odd ? t01 : t00);
            a[1] = __float_as_uint(odd ? t11 : t10);
            a[2] = __float_as_uint(odd ? t21 : t20);
            a[3] = __float_as_uint(odd ? t31 : t30);
#pragma unroll
            for (int nt = 0; nt < 16; ++nt) {
                const float* bb = Vsb + (ks * 8 + cl) * VSTR + nt * 8 + r;
                uint32_t b[2] = { __float_as_uint(bb[0]), __float_as_uint(bb[4 * VSTR]) };
                mma_tf32(accO[nt], a, b);
            }
        }
        __syncthreads();
        if (c + 2 < NCH) { issueKV(c + 2); CP_COMMIT(); }
    }

    // ---- finalize: O /= l, round, store ----
    const float inv0 = 1.0f / l0, inv1 = 1.0f / l1;
    float* O0 = g_attn + (size_t)(qb * 128 + ql0) * QDIM + h * HD;
    float* O1 = g_attn + (size_t)(qb * 128 + ql1) * QDIM + h * HD;
#pragma unroll
    for (int nt = 0; nt < 16; ++nt) {
        const int col = nt * 8 + 2 * cl;
        *(float2*)(O0 + col) = make_float2(to_tf32(accO[nt][0] * inv0),
                                           to_tf32(accO[nt][1] * inv0));
        *(float2*)(O1 + col) = make_float2(to_tf32(accO[nt][2] * inv1),
                                           to_tf32(accO[nt][3] * inv1));
    }
}

// ---------------- stage kernels ----------------
__global__ void zeropad_kernel() {
    int i = blockIdx.x * blockDim.x + threadIdx.x;
    if (i < WIN * KVDIM) { g_kpad[i] = 0.f; g_vpad[i] = 0.f; }
}

__global__ void round_tf32_kernel(const float* __restrict__ in, float* __restrict__ out, int n) {
    int i = (blockIdx.x * blockDim.x + threadIdx.x) * 4;
    if (i < n) {
        float4 v = *(const float4*)(in + i);
        v.x = to_tf32(v.x); v.y = to_tf32(v.y);
        v.z = to_tf32(v.z); v.w = to_tf32(v.w);
        *(float4*)(out + i) = v;
    }
}

__global__ __launch_bounds__(256)
void qproj_mma(void) {
    gemm_mma<false, true>(g_h, DMODEL, g_wq, QDIM, g_q, QDIM, DMODEL, blockIdx.x, blockIdx.y);
}
__global__ __launch_bounds__(256)
void kproj_mma(void) {
    gemm_mma<false, true>(g_h, DMODEL, g_wk, KVDIM, g_kpad + (size_t)WIN * KVDIM, KVDIM,
                          DMODEL, blockIdx.x, blockIdx.y);
}
__global__ __launch_bounds__(256)
void vproj_mma(void) {
    gemm_mma<false, true>(g_h, DMODEL, g_wv, KVDIM, g_vpad + (size_t)WIN * KVDIM, KVDIM,
                          DMODEL, blockIdx.x, blockIdx.y);
}
__global__ __launch_bounds__(256)
void oproj_mma(float* __restrict__ out) {
    gemm_mma<false, false>(g_attn, QDIM, g_wo, DMODEL, out, DMODEL, DMODEL,
                           blockIdx.x, blockIdx.y);
}

// ---------------- launcher (graph-capturable: kernels only) ----------------
extern "C" void kernel_launch(void* const* d_in, const int* in_sizes, int n_in,
                              void* d_out, int out_size) {
    const float* hidden = (const float*)d_in[0];
    const float* Wq = (const float*)d_in[1];
    const float* Wk = (const float*)d_in[2];
    const float* Wv = (const float*)d_in[3];
    const float* Wo = (const float*)d_in[4];
    float* out = (float*)d_out;

    float* gh; float* gwq; float* gwk; float* gwv; float* gwo;
    cudaGetSymbolAddress((void**)&gh,  g_h);
    cudaGetSymbolAddress((void**)&gwq, g_wq);
    cudaGetSymbolAddress((void**)&gwk, g_wk);
    cudaGetSymbolAddress((void**)&gwv, g_wv);
    cudaGetSymbolAddress((void**)&gwo, g_wo);

    cudaFuncSetAttribute(fattn_kernel, cudaFuncAttributeMaxDynamicSharedMemorySize,
                         FA_SMEM_BYTES);

    dim3 blk(256);
    // tf32-round all MMA inputs (zero-mean rounding; removes truncation bias)
    round_tf32_kernel<<<(S_LEN * DMODEL / 4 + 255) / 256, 256>>>(hidden, gh, S_LEN * DMODEL);
    round_tf32_kernel<<<(DMODEL * QDIM  / 4 + 255) / 256, 256>>>(Wq, gwq, DMODEL * QDIM);
    round_tf32_kernel<<<(DMODEL * KVDIM / 4 + 255) / 256, 256>>>(Wk, gwk, DMODEL * KVDIM);
    round_tf32_kernel<<<(DMODEL * KVDIM / 4 + 255) / 256, 256>>>(Wv, gwv, DMODEL * KVDIM);
    round_tf32_kernel<<<(QDIM * DMODEL  / 4 + 255) / 256, 256>>>(Wo, gwo, QDIM * DMODEL);
    zeropad_kernel<<<(WIN * KVDIM + 255) / 256, 256>>>();

    qproj_mma<<<dim3(QDIM / 128, S_LEN / 128), blk>>>();                 // (16,64)
    kproj_mma<<<dim3(KVDIM / 128, S_LEN / 128), blk>>>();                // (4,64)
    vproj_mma<<<dim3(KVDIM / 128, S_LEN / 128), blk>>>();                // (4,64)
    fattn_kernel<<<dim3(S_LEN / 128, HQN), blk, FA_SMEM_BYTES>>>();      // (64,16)
    oproj_mma<<<dim3(DMODEL / 128, S_LEN / 128), blk>>>(out);            // (16,64)
}

// round 7
// speedup vs baseline: 3.1795x; 1.1313x over previous
#include <cuda_runtime.h>
#include <cstdint>
#include <math.h>

#define S_LEN  8192
#define DMODEL 2048
#define HQN    16
#define HKVN   4
#define HD     128
#define WIN    512
#define KVDIM  (HKVN * HD)        /* 512 */
#define QDIM   (HQN * HD)        /* 2048 */

#define ASTR    20                /* A / BT-B smem row stride (floats) */
#define BSTR_NN 136               /* NN-B smem row stride (floats)     */
#define ASTG    (128 * ASTR)      /* A floats per stage: 2560 */
#define BSTG    2560              /* B floats per stage (covers both layouts) */
#define NSTAGE  4
#define GEMM_SMEM_BYTES (NSTAGE * (ASTG + BSTG) * 4)   /* 81920 B */

// ---------------- scratch (static device globals; no allocation) ----------------
__device__ float g_q[S_LEN * QDIM];                         // 64 MB (tf32, per-head cols)
__device__ float g_kpad[(S_LEN + WIN) * KVDIM];             // 17 MB (rows 0..511 zero)
__device__ float g_vpad[(S_LEN + WIN) * KVDIM];             // 17 MB
__device__ float g_attn[S_LEN * QDIM];                      // 64 MB
// tf32-rounded copies of inputs
__device__ float g_h[S_LEN * DMODEL];                       // 64 MB
__device__ float g_wq[DMODEL * QDIM];                       // 16 MB
__device__ float g_wk[DMODEL * KVDIM];                      //  4 MB
__device__ float g_wv[DMODEL * KVDIM];                      //  4 MB
__device__ float g_wo[QDIM * DMODEL];                       // 16 MB

// ---------------- helpers ----------------
__device__ __forceinline__ float to_tf32(float x) {
    uint32_t u;
    asm("cvt.rna.tf32.f32 %0, %1;" : "=r"(u) : "f"(x));
    return __uint_as_float(u);
}
__device__ __forceinline__ uint32_t smem_u32(const void* p) {
    uint32_t a;
    asm("{ .reg .u64 t; cvta.to.shared.u64 t, %1; cvt.u32.u64 %0, t; }" : "=r"(a) : "l"(p));
    return a;
}
__device__ __forceinline__ void cp16(uint32_t dst, const void* src) {
    asm volatile("cp.async.cg.shared.global [%0], [%1], 16;" :: "r"(dst), "l"(src) : "memory");
}
#define CP_COMMIT() asm volatile("cp.async.commit_group;" ::: "memory")
__device__ __forceinline__ void mma_tf32(float* c, const uint32_t* a, const uint32_t* b) {
    asm volatile(
        "mma.sync.aligned.m16n8k8.row.col.f32.tf32.tf32.f32 "
        "{%0,%1,%2,%3}, {%4,%5,%6,%7}, {%8,%9}, {%0,%1,%2,%3};"
        : "+f"(c[0]), "+f"(c[1]), "+f"(c[2]), "+f"(c[3])
        : "r"(a[0]), "r"(a[1]), "r"(a[2]), "r"(a[3]), "r"(b[0]), "r"(b[1]));
}

// ---------------- mma.sync tf32 128x128 GEMM tile, 4-stage cp.async pipeline ----------------
// C tile (by,bx) of: C = A * B   (BT=false: B is [K,N] row-major)
//                    C = A * B^T (BT=true:  B is [N,K] row-major)
// ROUND: round outputs to tf32 (when C feeds a later MMA as operand)
template <bool BT, bool ROUND>
__device__ __forceinline__ void gemm_mma(
    const float* __restrict__ A, int lda,
    const float* __restrict__ B, int ldb,
    float* __restrict__ C, int ldc,
    int K, int bx, int by)
{
    extern __shared__ float smdyn[];
    float* As = smdyn;                       // NSTAGE * ASTG floats
    float* Bs = smdyn + NSTAGE * ASTG;       // NSTAGE * BSTG floats

    const int tid = threadIdx.x;
    const int lane = tid & 31;
    const int w = tid >> 5;
    const int wm = (w & 3) * 32;
    const int wn = (w >> 2) * 64;

    const float* Ag = A + (size_t)(by * 128) * lda;
    const float* BgT = B + (size_t)(bx * 128) * ldb;
    const float* BgN = B + bx * 128;

    const uint32_t as_base = smem_u32(As);
    const uint32_t bs_base = smem_u32(Bs);

    const int arow = tid >> 1;
    const int acol = (tid & 1) * 8;
    const int bid = tid * 2;
    const int brow = bid >> 5;
    const int bcol = (bid & 31) * 4;

    float acc[2][8][4];
#pragma unroll
    for (int mt = 0; mt < 2; ++mt)
#pragma unroll
        for (int nt = 0; nt < 8; ++nt)
#pragma unroll
            for (int i = 0; i < 4; ++i) acc[mt][nt][i] = 0.f;

    const int nch = K >> 4;

    auto issue = [&](int c, int s) {
        const int k0 = c << 4;
        {
            const float* src = Ag + (size_t)arow * lda + k0 + acol;
            uint32_t d = as_base + (uint32_t)(s * ASTG + arow * ASTR + acol) * 4u;
            cp16(d, src);
            cp16(d + 16, src + 4);
        }
        if (BT) {
            const float* src = BgT + (size_t)arow * ldb + k0 + acol;
            uint32_t d = bs_base + (uint32_t)(s * BSTG + arow * ASTR + acol) * 4u;
            cp16(d, src);
            cp16(d + 16, src + 4);
        } else {
            const float* src = BgN + (size_t)(k0 + brow) * ldb + bcol;
            uint32_t d = bs_base + (uint32_t)(s * BSTG + brow * BSTR_NN + bcol) * 4u;
            cp16(d, src);
            cp16(d + 16, src + 4);
        }
        CP_COMMIT();
    };

    // prologue: stages 0..NSTAGE-2 in flight
#pragma unroll
    for (int c = 0; c < NSTAGE - 1; ++c)
        if (c < nch) issue(c, c);

    for (int c = 0; c < nch; ++c) {
        const int s = c & (NSTAGE - 1);
        asm volatile("cp.async.wait_group %0;" :: "n"(NSTAGE - 2) : "memory");
        __syncthreads();

        const float* Asb = As + s * ASTG;
        const float* Bsb = Bs + s * BSTG;
        const int r = lane >> 2, cc = lane & 3;
#pragma unroll
        for (int ks = 0; ks < 2; ++ks) {
            uint32_t a[2][4], b[8][2];
#pragma unroll
            for (int mt = 0; mt < 2; ++mt) {
                const float* ab = Asb + (wm + mt * 16 + r) * ASTR + ks * 8 + cc;
                a[mt][0] = __float_as_uint(ab[0]);
                a[mt][1] = __float_as_uint(ab[8 * ASTR]);
                a[mt][2] = __float_as_uint(ab[4]);
                a[mt][3] = __float_as_uint(ab[8 * ASTR + 4]);
            }
#pragma unroll
            for (int nt = 0; nt < 8; ++nt) {
                if (BT) {
                    const float* bb = Bsb + (wn + nt * 8 + r) * ASTR + ks * 8 + cc;
                    b[nt][0] = __float_as_uint(bb[0]);
                    b[nt][1] = __float_as_uint(bb[4]);
                } else {
                    const float* bb = Bsb + (ks * 8 + cc) * BSTR_NN + wn + nt * 8 + r;
                    b[nt][0] = __float_as_uint(bb[0]);
                    b[nt][1] = __float_as_uint(bb[4 * BSTR_NN]);
                }
            }
#pragma unroll
            for (int mt = 0; mt < 2; ++mt)
#pragma unroll
                for (int nt = 0; nt < 8; ++nt)
                    mma_tf32(acc[mt][nt], a[mt], b[nt]);
        }

        // refill the buffer freed in iteration c-1 (readers passed the sync above)
        if (c + NSTAGE - 1 < nch) issue(c + NSTAGE - 1, (c + NSTAGE - 1) & (NSTAGE - 1));
        else CP_COMMIT();   // keep group count exact at the tail
    }

    float* Cb = C + (size_t)(by * 128) * ldc + bx * 128;
    const int r = lane >> 2, c2 = (lane & 3) * 2;
#pragma unroll
    for (int mt = 0; mt < 2; ++mt) {
        const int row = wm + mt * 16 + r;
#pragma unroll
        for (int nt = 0; nt < 8; ++nt) {
            const int col = wn + nt * 8 + c2;
            float v0 = acc[mt][nt][0], v1 = acc[mt][nt][1];
            float v2 = acc[mt][nt][2], v3 = acc[mt][nt][3];
            if (ROUND) { v0 = to_tf32(v0); v1 = to_tf32(v1); v2 = to_tf32(v2); v3 = to_tf32(v3); }
            *(float2*)(Cb + (size_t)row * ldc + col) = make_float2(v0, v1);
            *(float2*)(Cb + (size_t)(row + 8) * ldc + col) = make_float2(v2, v3);
        }
    }
}

// ---------------- fused flash attention (band window, online softmax) ----------------
// grid (64 qblocks, 16 heads), 256 threads (8 warps x 16 query rows)
#define QSTR 132
#define KSTR 132
#define VSTR 136
#define SM_Q 0
#define SM_K (128 * QSTR)                       /* 16896 */
#define SM_V (SM_K + 2 * 64 * KSTR)             /* 33792 floats after SM_K */
#define FA_SMEM_FLOATS (SM_V + 2 * 64 * VSTR)   /* 51200 floats */
#define FA_SMEM_BYTES  (FA_SMEM_FLOATS * 4)     /* 204800 B */
#define NCH 10

__global__ __launch_bounds__(256, 1)
void fattn_kernel() {
    extern __shared__ float sm[];
    const int qb = blockIdx.x, h = blockIdx.y;
    const int tid = threadIdx.x, lane = tid & 31, w = tid >> 5;
    const uint32_t sbase = smem_u32(sm);

    const float* Qg = g_q + (size_t)(qb * 128) * QDIM + h * HD;
    const float* Kg = g_kpad + (size_t)(qb * 128) * KVDIM + (h >> 2) * HD;
    const float* Vg = g_vpad + (size_t)(qb * 128) * KVDIM + (h >> 2) * HD;

    const int qr = tid >> 1, qh = tid & 1;   // Q loader: row, half
    const int kr = tid >> 2, kq = tid & 3;   // K/V loader: row, quarter

    auto issueQ = [&]() {
        const float* src = Qg + (size_t)qr * QDIM + qh * 64;
        uint32_t d = sbase + (uint32_t)(qr * QSTR + qh * 64) * 4u;
#pragma unroll
        for (int j = 0; j < 8; ++j) {
            cp16(d + j * 32, src + j * 8);
            cp16(d + j * 32 + 16, src + j * 8 + 4);
        }
    };
    auto issueKV = [&](int c) {
        const int s = c & 1;
        const float* ks = Kg + (size_t)(c * 64 + kr) * KVDIM + kq * 32;
        uint32_t kd = sbase + (uint32_t)(SM_K + s * 64 * KSTR + kr * KSTR + kq * 32) * 4u;
#pragma unroll
        for (int j = 0; j < 8; ++j) cp16(kd + j * 16, ks + j * 4);
        const float* vs = Vg + (size_t)(c * 64 + kr) * KVDIM + kq * 32;
        uint32_t vd = sbase + (uint32_t)(SM_V + s * 64 * VSTR + kr * VSTR + kq * 32) * 4u;
#pragma unroll
        for (int j = 0; j < 8; ++j) cp16(vd + j * 16, vs + j * 4);
    };

    const int r = lane >> 2, cl = lane & 3;
    const int ql0 = w * 16 + r, ql1 = ql0 + 8;    // local query rows
    const int jmin = 512 - qb * 128;              // off >= jmin (key exists)
    const float scale = 1.0f / (float)HD;

    float accO[16][4];
#pragma unroll
    for (int nt = 0; nt < 16; ++nt)
#pragma unroll
        for (int i = 0; i < 4; ++i) accO[nt][i] = 0.f;
    float m0 = -3.0e38f, m1 = -3.0e38f, l0 = 0.f, l1 = 0.f;

    const int cstart = (qb < 4) ? (8 - 2 * qb) : 0;

    issueQ(); issueKV(cstart); CP_COMMIT();
    if (cstart + 1 < NCH) { issueKV(cstart + 1); CP_COMMIT(); }

#pragma unroll 1
    for (int c = cstart; c < NCH; ++c) {
        if (c + 1 < NCH) asm volatile("cp.async.wait_group 1;" ::: "memory");
        else             asm volatile("cp.async.wait_group 0;" ::: "memory");
        __syncthreads();
        const int s = c & 1;
        const float* Ksb = sm + SM_K + s * 64 * KSTR;
        const float* Vsb = sm + SM_V + s * 64 * VSTR;

        // ---- S = Q (128xHD) * Kchunk(64xHD)^T ----
        float accS[8][4];
#pragma unroll
        for (int nt = 0; nt < 8; ++nt)
#pragma unroll
            for (int i = 0; i < 4; ++i) accS[nt][i] = 0.f;
#pragma unroll
        for (int ks = 0; ks < 16; ++ks) {
            uint32_t a[4];
            const float* ab = sm + (w * 16 + r) * QSTR + ks * 8 + cl;
            a[0] = __float_as_uint(ab[0]);
            a[1] = __float_as_uint(ab[8 * QSTR]);
            a[2] = __float_as_uint(ab[4]);
            a[3] = __float_as_uint(ab[8 * QSTR + 4]);
#pragma unroll
            for (int nt = 0; nt < 8; ++nt) {
                const float* bb = Ksb + (nt * 8 + r) * KSTR + ks * 8 + cl;
                uint32_t b[2] = { __float_as_uint(bb[0]), __float_as_uint(bb[4]) };
                mma_tf32(accS[nt], a, b);
            }
        }

        // ---- band mask + chunk row max ----
        float mc0 = -3.0e38f, mc1 = -3.0e38f;
#pragma unroll
        for (int nt = 0; nt < 8; ++nt) {
            const int off0 = c * 64 + nt * 8 + 2 * cl;
            const int off1 = off0 + 1;
            bool v00 = (off0 > ql0) && (off0 <= ql0 + 512) && (off0 >= jmin);
            bool v01 = (off1 > ql0) && (off1 <= ql0 + 512) && (off1 >= jmin);
            bool v10 = (off0 > ql1) && (off0 <= ql1 + 512) && (off0 >= jmin);
            bool v11 = (off1 > ql1) && (off1 <= ql1 + 512) && (off1 >= jmin);
            accS[nt][0] = v00 ? accS[nt][0] : -3.0e38f;
            accS[nt][1] = v01 ? accS[nt][1] : -3.0e38f;
            accS[nt][2] = v10 ? accS[nt][2] : -3.0e38f;
            accS[nt][3] = v11 ? accS[nt][3] : -3.0e38f;
            mc0 = fmaxf(mc0, fmaxf(accS[nt][0], accS[nt][1]));
            mc1 = fmaxf(mc1, fmaxf(accS[nt][2], accS[nt][3]));
        }
        mc0 = fmaxf(mc0, __shfl_xor_sync(0xffffffffu, mc0, 1));
        mc0 = fmaxf(mc0, __shfl_xor_sync(0xffffffffu, mc0, 2));
        mc1 = fmaxf(mc1, __shfl_xor_sync(0xffffffffu, mc1, 1));
        mc1 = fmaxf(mc1, __shfl_xor_sync(0xffffffffu, mc1, 2));

        // ---- online softmax update ----
        const float mn0 = fmaxf(m0, mc0), mn1 = fmaxf(m1, mc1);
        const float f0 = __expf((m0 - mn0) * scale);
        const float f1 = __expf((m1 - mn1) * scale);
        float s0 = 0.f, s1 = 0.f;
#pragma unroll
        for (int nt = 0; nt < 8; ++nt) {
            float e0 = (accS[nt][0] > -1.0e38f) ? __expf((accS[nt][0] - mn0) * scale) : 0.f;
            float e1 = (accS[nt][1] > -1.0e38f) ? __expf((accS[nt][1] - mn0) * scale) : 0.f;
            float e2 = (accS[nt][2] > -1.0e38f) ? __expf((accS[nt][2] - mn1) * scale) : 0.f;
            float e3 = (accS[nt][3] > -1.0e38f) ? __expf((accS[nt][3] - mn1) * scale) : 0.f;
            s0 += e0 + e1; s1 += e2 + e3;
            accS[nt][0] = to_tf32(e0); accS[nt][1] = to_tf32(e1);
            accS[nt][2] = to_tf32(e2); accS[nt][3] = to_tf32(e3);
        }
        s0 += __shfl_xor_sync(0xffffffffu, s0, 1);
        s0 += __shfl_xor_sync(0xffffffffu, s0, 2);
        s1 += __shfl_xor_sync(0xffffffffu, s1, 1);
        s1 += __shfl_xor_sync(0xffffffffu, s1, 2);
        l0 = l0 * f0 + s0; l1 = l1 * f1 + s1;
        m0 = mn0; m1 = mn1;
#pragma unroll
        for (int nt = 0; nt < 16; ++nt) {
            accO[nt][0] *= f0; accO[nt][1] *= f0;
            accO[nt][2] *= f1; accO[nt][3] *= f1;
        }

        // ---- O += P (128x64) * Vchunk (64xHD) ----
        const uint32_t srcl0 = (lane & ~3u) | ((uint32_t)(lane & 3) >> 1);
        const uint32_t srcl1 = srcl0 + 2;
        const bool odd = lane & 1;
#pragma unroll
        for (int ks = 0; ks < 8; ++ks) {
            // convert C-frag cols {2c,2c+1} -> A-frag cols {c, c+4} via shuffles
            float p0 = accS[ks][0], p1 = accS[ks][1];
            float p2 = accS[ks][2], p3 = accS[ks][3];
            float t00 = __shfl_sync(0xffffffffu, p0, srcl0);
            float t01 = __shfl_sync(0xffffffffu, p1, srcl0);
            float t10 = __shfl_sync(0xffffffffu, p2, srcl0);
            float t11 = __shfl_sync(0xffffffffu, p3, srcl0);
            float t20 = __shfl_sync(0xffffffffu, p0, srcl1);
            float t21 = __shfl_sync(0xffffffffu, p1, srcl1);
            float t30 = __shfl_sync(0xffffffffu, p2, srcl1);
            float t31 = __shfl_sync(0xffffffffu, p3, srcl1);
            uint32_t a[4];
            a[0] = __float_as_uint(odd ? t01 : t00);
            a[1] = __float_as_uint(odd ? t11 : t10);
            a[2] = __float_as_uint(odd ? t21 : t20);
            a[3] = __float_as_uint(odd ? t31 : t30);
#pragma unroll
            for (int nt = 0; nt < 16; ++nt) {
                const float* bb = Vsb + (ks * 8 + cl) * VSTR + nt * 8 + r;
                uint32_t b[2] = { __float_as_uint(bb[0]), __float_as_uint(bb[4 * VSTR]) };
                mma_tf32(accO[nt], a, b);
            }
        }
        __syncthreads();
        if (c + 2 < NCH) { issueKV(c + 2); CP_COMMIT(); }
    }

    // ---- finalize: O /= l, round, store ----
    const float inv0 = 1.0f / l0, inv1 = 1.0f / l1;
    float* O0 = g_attn + (size_t)(qb * 128 + ql0) * QDIM + h * HD;
    float* O1 = g_attn + (size_t)(qb * 128 + ql1) * QDIM + h * HD;
#pragma unroll
    for (int nt = 0; nt < 16; ++nt) {
        const int col = nt * 8 + 2 * cl;
        *(float2*)(O0 + col) = make_float2(to_tf32(accO[nt][0] * inv0),
                                           to_tf32(accO[nt][1] * inv0));
        *(float2*)(O1 + col) = make_float2(to_tf32(accO[nt][2] * inv1),
                                           to_tf32(accO[nt][3] * inv1));
    }
}

// ---------------- stage kernels ----------------
__global__ void zeropad_kernel() {
    int i = blockIdx.x * blockDim.x + threadIdx.x;
    if (i < WIN * KVDIM) { g_kpad[i] = 0.f; g_vpad[i] = 0.f; }
}

__global__ void round_tf32_kernel(const float* __restrict__ in, float* __restrict__ out, int n) {
    int i = (blockIdx.x * blockDim.x + threadIdx.x) * 4;
    if (i < n) {
        float4 v = *(const float4*)(in + i);
        v.x = to_tf32(v.x); v.y = to_tf32(v.y);
        v.z = to_tf32(v.z); v.w = to_tf32(v.w);
        *(float4*)(out + i) = v;
    }
}

__global__ __launch_bounds__(256)
void qproj_mma(void) {
    gemm_mma<false, true>(g_h, DMODEL, g_wq, QDIM, g_q, QDIM, DMODEL, blockIdx.x, blockIdx.y);
}
__global__ __launch_bounds__(256)
void kproj_mma(void) {
    gemm_mma<false, true>(g_h, DMODEL, g_wk, KVDIM, g_kpad + (size_t)WIN * KVDIM, KVDIM,
                          DMODEL, blockIdx.x, blockIdx.y);
}
__global__ __launch_bounds__(256)
void vproj_mma(void) {
    gemm_mma<false, true>(g_h, DMODEL, g_wv, KVDIM, g_vpad + (size_t)WIN * KVDIM, KVDIM,
                          DMODEL, blockIdx.x, blockIdx.y);
}
__global__ __launch_bounds__(256)
void oproj_mma(float* __restrict__ out) {
    gemm_mma<false, false>(g_attn, QDIM, g_wo, DMODEL, out, DMODEL, DMODEL,
                           blockIdx.x, blockIdx.y);
}

// ---------------- launcher (graph-capturable: kernels only) ----------------
extern "C" void kernel_launch(void* const* d_in, const int* in_sizes, int n_in,
                              void* d_out, int out_size) {
    const float* hidden = (const float*)d_in[0];
    const float* Wq = (const float*)d_in[1];
    const float* Wk = (const float*)d_in[2];
    const float* Wv = (const float*)d_in[3];
    const float* Wo = (const float*)d_in[4];
    float* out = (float*)d_out;

    float* gh; float* gwq; float* gwk; float* gwv; float* gwo;
    cudaGetSymbolAddress((void**)&gh,  g_h);
    cudaGetSymbolAddress((void**)&gwq, g_wq);
    cudaGetSymbolAddress((void**)&gwk, g_wk);
    cudaGetSymbolAddress((void**)&gwv, g_wv);
    cudaGetSymbolAddress((void**)&gwo, g_wo);

    cudaFuncSetAttribute(fattn_kernel, cudaFuncAttributeMaxDynamicSharedMemorySize,
                         FA_SMEM_BYTES);
    cudaFuncSetAttribute(qproj_mma, cudaFuncAttributeMaxDynamicSharedMemorySize, GEMM_SMEM_BYTES);
    cudaFuncSetAttribute(kproj_mma, cudaFuncAttributeMaxDynamicSharedMemorySize, GEMM_SMEM_BYTES);
    cudaFuncSetAttribute(vproj_mma, cudaFuncAttributeMaxDynamicSharedMemorySize, GEMM_SMEM_BYTES);
    cudaFuncSetAttribute(oproj_mma, cudaFuncAttributeMaxDynamicSharedMemorySize, GEMM_SMEM_BYTES);

    dim3 blk(256);
    // tf32-round all MMA inputs (zero-mean rounding; removes truncation bias)
    round_tf32_kernel<<<(S_LEN * DMODEL / 4 + 255) / 256, 256>>>(hidden, gh, S_LEN * DMODEL);
    round_tf32_kernel<<<(DMODEL * QDIM  / 4 + 255) / 256, 256>>>(Wq, gwq, DMODEL * QDIM);
    round_tf32_kernel<<<(DMODEL * KVDIM / 4 + 255) / 256, 256>>>(Wk, gwk, DMODEL * KVDIM);
    round_tf32_kernel<<<(DMODEL * KVDIM / 4 + 255) / 256, 256>>>(Wv, gwv, DMODEL * KVDIM);
    round_tf32_kernel<<<(QDIM * DMODEL  / 4 + 255) / 256, 256>>>(Wo, gwo, QDIM * DMODEL);
    zeropad_kernel<<<(WIN * KVDIM + 255) / 256, 256>>>();

    qproj_mma<<<dim3(QDIM / 128, S_LEN / 128), blk, GEMM_SMEM_BYTES>>>();   // (16,64)
    kproj_mma<<<dim3(KVDIM / 128, S_LEN / 128), blk, GEMM_SMEM_BYTES>>>();  // (4,64)
    vproj_mma<<<dim3(KVDIM / 128, S_LEN / 128), blk, GEMM_SMEM_BYTES>>>();  // (4,64)
    fattn_kernel<<<dim3(S_LEN / 128, HQN), blk, FA_SMEM_BYTES>>>();         // (64,16)
    oproj_mma<<<dim3(DMODEL / 128, S_LEN / 128), blk, GEMM_SMEM_BYTES>>>(out); // (16,64)
}